// round 1
// baseline (speedup 1.0000x reference)
#include <cuda_runtime.h>

// Problem constants (from reference)
#define B_  128
#define G_  20000
#define P_  4096
#define KT  32          // K chunk per smem stage
#define NT  32          // columns per CTA
#define NCTA (P_/NT)    // 128 CTAs
#define BN_EPS 1e-5f

// Scratch for cross-CTA decision reduction: [NCTA][B_] partial row sums.
__device__ float g_dpart[NCTA * B_];

__global__ __launch_bounds__(256) void bioxnet_fused_kernel(
    const float* __restrict__ A,        // [B, G]
    const float* __restrict__ mapp,     // [G, P]
    const float* __restrict__ Wk,       // [G, P] kernel
    const float* __restrict__ bias,     // [P]
    const float* __restrict__ Wa,       // [G, P] att_kernel
    const float* __restrict__ att_bias, // [P]
    const float* __restrict__ gamma,    // [P]
    const float* __restrict__ beta,     // [P]
    const float* __restrict__ dec_w,    // [P]
    float* __restrict__ out_outcome,    // [B, P]
    float* __restrict__ out_att)        // [B, P]
{
    // A tile stored k-major (transposed) so the mainloop reads 4 consecutive
    // rows as one float4. Pad 132 keeps 16B alignment and kills read conflicts.
    __shared__ __align__(16) float As[KT][132];
    __shared__ __align__(16) float Wm[KT][NT];   // kernel * mapp (mask fused at load)
    __shared__ __align__(16) float Wt[KT][NT];   // att_kernel
    __shared__ float redS[32][NT];
    __shared__ float redQ[32][NT];
    __shared__ float4 dsm[32][8];
    __shared__ float s_mean[NT];
    __shared__ float s_rstd[NT];

    const int tid  = threadIdx.x;
    const int tx   = tid & 7;    // 0..7  -> column group (4 cols each)
    const int ty   = tid >> 3;   // 0..31 -> row group   (4 rows each)
    const int col0 = blockIdx.x * NT;

    float accH[4][4];
    float accT[4][4];
#pragma unroll
    for (int r = 0; r < 4; r++)
#pragma unroll
        for (int c = 0; c < 4; c++) { accH[r][c] = 0.f; accT[r][c] = 0.f; }

    for (int kk = 0; kk < G_; kk += KT) {
        // ---- Load A chunk [128 rows x 32 k], transpose into As[k][row] ----
#pragma unroll
        for (int i = 0; i < 4; i++) {
            int idx = tid + i * 256;          // 0..1023 float4 slots
            int row = idx >> 3;               // 0..127
            int kv  = idx & 7;                // float4 index along k
            float4 v = *(const float4*)(A + (long)row * G_ + kk + kv * 4);
            As[kv * 4 + 0][row] = v.x;
            As[kv * 4 + 1][row] = v.y;
            As[kv * 4 + 2][row] = v.z;
            As[kv * 4 + 3][row] = v.w;
        }
        // ---- Load weight chunks [32 k x 32 cols], fuse mask multiply ----
        {
            int kr = tid >> 3;                 // 0..31 k row
            int cv = tid & 7;                  // float4 col slot
            long goff = (long)(kk + kr) * P_ + col0 + cv * 4;
            float4 wk4 = *(const float4*)(Wk   + goff);
            float4 m4  = *(const float4*)(mapp + goff);
            float4 wa4 = *(const float4*)(Wa   + goff);
            wk4.x *= m4.x; wk4.y *= m4.y; wk4.z *= m4.z; wk4.w *= m4.w;
            *(float4*)&Wm[kr][cv * 4] = wk4;
            *(float4*)&Wt[kr][cv * 4] = wa4;
        }
        __syncthreads();

        // ---- Register-tiled dual FMA mainloop ----
#pragma unroll 8
        for (int k = 0; k < KT; k++) {
            float4 a4 = *(const float4*)&As[k][ty * 4];
            float4 w4 = *(const float4*)&Wm[k][tx * 4];
            float4 t4 = *(const float4*)&Wt[k][tx * 4];
            float a[4] = {a4.x, a4.y, a4.z, a4.w};
            float w[4] = {w4.x, w4.y, w4.z, w4.w};
            float t[4] = {t4.x, t4.y, t4.z, t4.w};
#pragma unroll
            for (int r = 0; r < 4; r++) {
#pragma unroll
                for (int c = 0; c < 4; c++) {
                    accH[r][c] = fmaf(a[r], w[c], accH[r][c]);
                    accT[r][c] = fmaf(a[r], t[c], accT[r][c]);
                }
            }
        }
        __syncthreads();
    }

    // ---- Per-column params ----
    float bcol[4], abcol[4], gcol[4], btcol[4], dwcol[4];
#pragma unroll
    for (int c = 0; c < 4; c++) {
        int p = col0 + tx * 4 + c;
        bcol[c]  = bias[p];
        abcol[c] = att_bias[p];
        gcol[c]  = gamma[p];
        btcol[c] = beta[p];
        dwcol[c] = dec_w[p];
    }
#pragma unroll
    for (int r = 0; r < 4; r++)
#pragma unroll
        for (int c = 0; c < 4; c++) accH[r][c] += bcol[c];

    // ---- BatchNorm stats: reduce over the 128 rows (all in this CTA) ----
#pragma unroll
    for (int c = 0; c < 4; c++) {
        float s = 0.f, q = 0.f;
#pragma unroll
        for (int r = 0; r < 4; r++) {
            float h = accH[r][c];
            s += h;
            q += h * h;
        }
        redS[ty][tx * 4 + c] = s;
        redQ[ty][tx * 4 + c] = q;
    }
    __syncthreads();
    if (tid < NT) {
        float s = 0.f, q = 0.f;
#pragma unroll
        for (int i = 0; i < 32; i++) { s += redS[i][tid]; q += redQ[i][tid]; }
        float mean = s * (1.0f / B_);
        float var  = q * (1.0f / B_) - mean * mean;
        s_mean[tid] = mean;
        s_rstd[tid] = rsqrtf(var + BN_EPS);
    }
    __syncthreads();

    // ---- Apply BN, tanh, sigmoid gate; write outputs; decision partials ----
    float dp[4];
#pragma unroll
    for (int r = 0; r < 4; r++) {
        int row = ty * 4 + r;
        float oc[4], ap[4];
        float dsum = 0.f;
#pragma unroll
        for (int c = 0; c < 4; c++) {
            int ci = tx * 4 + c;
            float hn = (accH[r][c] - s_mean[ci]) * s_rstd[ci] * gcol[c] + btcol[c];
            float th = tanhf(hn);
            float sg = 1.0f / (1.0f + __expf(-(accT[r][c] + abcol[c])));
            float o  = th * sg;
            oc[c] = o;
            ap[c] = sg;
            dsum = fmaf(o, dwcol[c], dsum);
        }
        long o_off = (long)row * P_ + col0 + tx * 4;
        *(float4*)(out_outcome + o_off) = make_float4(oc[0], oc[1], oc[2], oc[3]);
        *(float4*)(out_att     + o_off) = make_float4(ap[0], ap[1], ap[2], ap[3]);
        dp[r] = dsum;
    }
    dsm[ty][tx] = make_float4(dp[0], dp[1], dp[2], dp[3]);
    __syncthreads();
    if (tid < B_) {
        int row = tid;
        int tg = row >> 2;
        int j  = row & 3;
        float s = 0.f;
#pragma unroll
        for (int x = 0; x < 8; x++) {
            float4 v = dsm[tg][x];
            s += (&v.x)[j];
        }
        g_dpart[blockIdx.x * B_ + row] = s;
    }
}

__global__ void bioxnet_decision_kernel(const float* __restrict__ dec_b,
                                        float* __restrict__ out_dec)
{
    int r = threadIdx.x;   // 0..127
    float s = dec_b[0];
#pragma unroll 8
    for (int c = 0; c < NCTA; c++) s += g_dpart[c * B_ + r];
    out_dec[r] = s;
}

extern "C" void kernel_launch(void* const* d_in, const int* in_sizes, int n_in,
                              void* d_out, int out_size)
{
    (void)in_sizes; (void)n_in; (void)out_size;
    const float* A        = (const float*)d_in[0];
    const float* mapp     = (const float*)d_in[1];
    const float* Wk       = (const float*)d_in[2];
    const float* bias     = (const float*)d_in[3];
    const float* Wa       = (const float*)d_in[4];
    const float* att_bias = (const float*)d_in[5];
    const float* gamma    = (const float*)d_in[6];
    const float* beta     = (const float*)d_in[7];
    const float* dec_w    = (const float*)d_in[8];
    const float* dec_b    = (const float*)d_in[9];

    float* out = (float*)d_out;
    float* out_outcome = out;                       // [B, P]
    float* out_dec     = out + (long)B_ * P_;       // [B, 1]
    float* out_att     = out + (long)B_ * P_ + B_;  // [B, P]

    bioxnet_fused_kernel<<<NCTA, 256>>>(A, mapp, Wk, bias, Wa, att_bias,
                                        gamma, beta, dec_w,
                                        out_outcome, out_att);
    bioxnet_decision_kernel<<<1, B_>>>(dec_b, out_dec);
}

// round 2
// speedup vs baseline: 1.1886x; 1.1886x over previous
#include <cuda_runtime.h>
#include <cuda_bf16.h>
#include <stdint.h>

// Problem constants
#define B_  128
#define G_  20000
#define P_  4096
#define KT  32          // K chunk per smem stage
#define NT  32          // columns per CTA
#define NCTA (P_/NT)    // 128 CTAs
#define BN_EPS 1e-5f

#define SA 20   // u32-word stride of A rows in smem (40 bf16)
#define SW 20   // u32-word stride of W cols in smem (40 bf16)
#define SHS 34  // f32 stride of epilogue tiles

// Decision partials, [row][cta] for coalesced reduction.
__device__ float g_dpart[B_ * NCTA];

__device__ __forceinline__ void split2(float x, float y, uint32_t& hi, uint32_t& lo) {
    __nv_bfloat16 xh = __float2bfloat16_rn(x);
    __nv_bfloat16 yh = __float2bfloat16_rn(y);
    float xr = x - __bfloat162float(xh);
    float yr = y - __bfloat162float(yh);
    __nv_bfloat16 xl = __float2bfloat16_rn(xr);
    __nv_bfloat16 yl = __float2bfloat16_rn(yr);
    hi = ((uint32_t)(*(uint16_t*)&yh) << 16) | (uint32_t)(*(uint16_t*)&xh);
    lo = ((uint32_t)(*(uint16_t*)&yl) << 16) | (uint32_t)(*(uint16_t*)&xl);
}

__device__ __forceinline__ void split1(float x, uint16_t& hi, uint16_t& lo) {
    __nv_bfloat16 xh = __float2bfloat16_rn(x);
    float xr = x - __bfloat162float(xh);
    __nv_bfloat16 xl = __float2bfloat16_rn(xr);
    hi = *(uint16_t*)&xh;
    lo = *(uint16_t*)&xl;
}

__device__ __forceinline__ void mma_bf16(float* d, const uint32_t* a, uint32_t b0, uint32_t b1) {
    asm volatile(
        "mma.sync.aligned.m16n8k16.row.col.f32.bf16.bf16.f32 "
        "{%0,%1,%2,%3}, {%4,%5,%6,%7}, {%8,%9}, {%0,%1,%2,%3};"
        : "+f"(d[0]), "+f"(d[1]), "+f"(d[2]), "+f"(d[3])
        : "r"(a[0]), "r"(a[1]), "r"(a[2]), "r"(a[3]), "r"(b0), "r"(b1));
}

__global__ __launch_bounds__(256) void bioxnet_fused_kernel(
    const float* __restrict__ A,        // [B, G]
    const float* __restrict__ mapp,     // [G, P]
    const float* __restrict__ Wk,       // [G, P]
    const float* __restrict__ Wa,       // [G, P]
    const float* __restrict__ att_bias, // [P]
    const float* __restrict__ gamma,    // [P]
    const float* __restrict__ beta,     // [P]
    const float* __restrict__ dec_w,    // [P]
    float* __restrict__ out_outcome,    // [B, P]
    float* __restrict__ out_att)        // [B, P]
{
    // Shared buffer, reused between mainloop and epilogue.
    // Mainloop (u32 words): Ahi[0,2560) Alo[2560,5120) Whi[5120,5760)
    //                       Wlo[5760,6400) Thi[6400,7040) Tlo[7040,7680)
    // Epilogue (f32):       sH[0,4352) sT[4352,8704)
    __shared__ __align__(16) uint32_t sbuf[8704];
    __shared__ float redS[8][NT];
    __shared__ float redQ[8][NT];
    __shared__ float s_mean[NT];
    __shared__ float s_rstd[NT];

    uint32_t* sAhi = sbuf;
    uint32_t* sAlo = sbuf + 2560;
    uint32_t* sWhi = sbuf + 5120;
    uint32_t* sWlo = sbuf + 5760;
    uint32_t* sThi = sbuf + 6400;
    uint32_t* sTlo = sbuf + 7040;

    const int tid  = threadIdx.x;
    const int lane = tid & 31;
    const int wrp  = tid >> 5;     // 0..7, owns rows [16*wrp, 16*wrp+16)
    const int gr   = lane >> 2;    // 0..7
    const int tc   = lane & 3;     // 0..3
    const int w16  = wrp * 16;
    const int col0 = blockIdx.x * NT;

    float accH[4][4];
    float accT[4][4];
#pragma unroll
    for (int nt = 0; nt < 4; nt++)
#pragma unroll
        for (int i = 0; i < 4; i++) { accH[nt][i] = 0.f; accT[nt][i] = 0.f; }

#pragma unroll 1
    for (int kk = 0; kk < G_; kk += KT) {
        // ---- Load + split A chunk [128 x 32] -> bf16 hi/lo, layout [row][k] ----
#pragma unroll
        for (int i = 0; i < 4; i++) {
            int idx = tid + i * 256;
            int row = idx >> 3;
            int kv  = idx & 7;
            float4 v = *(const float4*)(A + (long)row * G_ + kk + kv * 4);
            uint32_t h0, l0, h1, l1;
            split2(v.x, v.y, h0, l0);
            split2(v.z, v.w, h1, l1);
            int wofs = row * SA + kv * 2;
            sAhi[wofs] = h0; sAhi[wofs + 1] = h1;
            sAlo[wofs] = l0; sAlo[wofs + 1] = l1;
        }
        // ---- Load + split W (masked) and T chunks, transposed to [n][k] ----
        {
            int kr = tid >> 3;
            int nv = tid & 7;
            long g = (long)(kk + kr) * P_ + col0 + nv * 4;
            float4 wk = *(const float4*)(Wk + g);
            float4 mp = *(const float4*)(mapp + g);
            float4 wa = *(const float4*)(Wa + g);
            wk.x *= mp.x; wk.y *= mp.y; wk.z *= mp.z; wk.w *= mp.w;
            uint16_t* Whi16 = (uint16_t*)sWhi;
            uint16_t* Wlo16 = (uint16_t*)sWlo;
            uint16_t* Thi16 = (uint16_t*)sThi;
            uint16_t* Tlo16 = (uint16_t*)sTlo;
#pragma unroll
            for (int j = 0; j < 4; j++) {
                int n = nv * 4 + j;
                uint16_t h, l;
                split1((&wk.x)[j], h, l);
                Whi16[n * 40 + kr] = h;
                Wlo16[n * 40 + kr] = l;
                split1((&wa.x)[j], h, l);
                Thi16[n * 40 + kr] = h;
                Tlo16[n * 40 + kr] = l;
            }
        }
        __syncthreads();

        // ---- MMA mainloop: 2 k16 steps, 4 n-tiles, 3-pass split x 2 GEMMs ----
#pragma unroll
        for (int kh = 0; kh < 16; kh += 8) {   // kh = ks/2
            uint32_t ahi[4], alo[4];
            int ab = (w16 + gr) * SA + kh + tc;
            ahi[0] = sAhi[ab];              alo[0] = sAlo[ab];
            ahi[1] = sAhi[ab + 8 * SA];     alo[1] = sAlo[ab + 8 * SA];
            ahi[2] = sAhi[ab + 4];          alo[2] = sAlo[ab + 4];
            ahi[3] = sAhi[ab + 8 * SA + 4]; alo[3] = sAlo[ab + 8 * SA + 4];
#pragma unroll
            for (int nt = 0; nt < 4; nt++) {
                int bb = (nt * 8 + gr) * SW + kh + tc;
                uint32_t wh0 = sWhi[bb], wh1 = sWhi[bb + 4];
                uint32_t wl0 = sWlo[bb], wl1 = sWlo[bb + 4];
                uint32_t th0 = sThi[bb], th1 = sThi[bb + 4];
                uint32_t tl0 = sTlo[bb], tl1 = sTlo[bb + 4];
                mma_bf16(accH[nt], ahi, wh0, wh1);
                mma_bf16(accH[nt], ahi, wl0, wl1);
                mma_bf16(accH[nt], alo, wh0, wh1);
                mma_bf16(accT[nt], ahi, th0, th1);
                mma_bf16(accT[nt], ahi, tl0, tl1);
                mma_bf16(accT[nt], alo, th0, th1);
            }
        }
        __syncthreads();
    }

    // ---- Spill fragments to smem (epilogue needs column-major access) ----
    // Note: GEMM bias is omitted — it cancels exactly in batchnorm mean-subtract.
    float* sH = (float*)sbuf;
    float* sT = (float*)(sbuf + 4352);
#pragma unroll
    for (int nt = 0; nt < 4; nt++) {
        int col = nt * 8 + 2 * tc;
        int r0 = w16 + gr, r1 = r0 + 8;
        *(float2*)&sH[r0 * SHS + col] = make_float2(accH[nt][0], accH[nt][1]);
        *(float2*)&sH[r1 * SHS + col] = make_float2(accH[nt][2], accH[nt][3]);
        *(float2*)&sT[r0 * SHS + col] = make_float2(accT[nt][0], accT[nt][1]);
        *(float2*)&sT[r1 * SHS + col] = make_float2(accT[nt][2], accT[nt][3]);
    }
    __syncthreads();

    // ---- BatchNorm stats over the 128 rows (all in this CTA) ----
    const int col = tid & 31;
    const int seg = tid >> 5;
    {
        float s = 0.f, q = 0.f;
#pragma unroll
        for (int r = 0; r < 16; r++) {
            float h = sH[(seg * 16 + r) * SHS + col];
            s += h; q += h * h;
        }
        redS[seg][col] = s;
        redQ[seg][col] = q;
    }
    __syncthreads();
    if (tid < 32) {
        float ss = 0.f, qq = 0.f;
#pragma unroll
        for (int i = 0; i < 8; i++) { ss += redS[i][tid]; qq += redQ[i][tid]; }
        float mean = ss * (1.0f / B_);
        float var  = qq * (1.0f / B_) - mean * mean;
        s_mean[tid] = mean;
        s_rstd[tid] = rsqrtf(var + BN_EPS);
    }
    __syncthreads();

    // ---- Apply BN + tanh + sigmoid gate, write outputs, decision partials ----
    const float mean = s_mean[col];
    const float rstd = s_rstd[col];
    const float gm = gamma[col0 + col];
    const float bt = beta[col0 + col];
    const float ab = att_bias[col0 + col];
    const float dw = dec_w[col0 + col];
#pragma unroll 4
    for (int r = 0; r < 16; r++) {
        int row = seg * 16 + r;
        float h  = sH[row * SHS + col];
        float hn = (h - mean) * rstd * gm + bt;
        float th = tanhf(hn);
        float z  = sT[row * SHS + col] + ab;
        float sg = 1.0f / (1.0f + __expf(-z));
        float o  = th * sg;
        long ofs = (long)row * P_ + col0 + col;
        out_outcome[ofs] = o;
        out_att[ofs]     = sg;
        // warp = 32 cols of one row -> full row reduction via shuffle
        float p = o * dw;
#pragma unroll
        for (int off = 16; off > 0; off >>= 1)
            p += __shfl_xor_sync(0xffffffffu, p, off);
        if (col == 0) g_dpart[row * NCTA + blockIdx.x] = p;
    }
}

__global__ __launch_bounds__(512) void bioxnet_decision_kernel(
    const float* __restrict__ dec_b, float* __restrict__ out_dec)
{
    __shared__ float red[4][B_];
    int t = threadIdx.x;          // 512 threads
    int row = t >> 2;             // 0..127
    int seg = t & 3;              // 0..3, each covers 32 ctas = 8 float4
    const float4* p = (const float4*)(g_dpart + row * NCTA + seg * 32);
    float s = 0.f;
#pragma unroll
    for (int i = 0; i < 8; i++) {
        float4 v = p[i];
        s += v.x + v.y + v.z + v.w;
    }
    red[seg][row] = s;
    __syncthreads();
    if (t < B_) {
        out_dec[t] = dec_b[0] + red[0][t] + red[1][t] + red[2][t] + red[3][t];
    }
}

extern "C" void kernel_launch(void* const* d_in, const int* in_sizes, int n_in,
                              void* d_out, int out_size)
{
    (void)in_sizes; (void)n_in; (void)out_size;
    const float* A        = (const float*)d_in[0];
    const float* mapp     = (const float*)d_in[1];
    const float* Wk       = (const float*)d_in[2];
    // d_in[3] = bias: cancels exactly in batchnorm, unused
    const float* Wa       = (const float*)d_in[4];
    const float* att_bias = (const float*)d_in[5];
    const float* gamma    = (const float*)d_in[6];
    const float* beta     = (const float*)d_in[7];
    const float* dec_w    = (const float*)d_in[8];
    const float* dec_b    = (const float*)d_in[9];

    float* out = (float*)d_out;
    float* out_outcome = out;                       // [B, P]
    float* out_dec     = out + (long)B_ * P_;       // [B, 1]
    float* out_att     = out + (long)B_ * P_ + B_;  // [B, P]

    bioxnet_fused_kernel<<<NCTA, 256>>>(A, mapp, Wk, Wa, att_bias,
                                        gamma, beta, dec_w,
                                        out_outcome, out_att);
    bioxnet_decision_kernel<<<1, 512>>>(dec_b, out_dec);
}

// round 3
// speedup vs baseline: 2.4405x; 2.0533x over previous
#include <cuda_runtime.h>
#include <cuda_bf16.h>
#include <stdint.h>

#define B_  128
#define G_  20000
#define P_  4096
#define KT  32
#define NT  32
#define NCTA   (P_/NT)    // 128
#define NCHUNK (G_/KT)    // 625
#define BN_EPS 1e-5f

// smem u32 strides
#define SA  16   // A row stride (32 bf16, no pad)
#define SWW 17   // W col stride (34 bf16, padded)
#define SHS 34   // epilogue f32 stride

// smem u32 layout offsets
#define A_STAGE 4096          // one A stage = hi(2048) + lo(2048)
#define A_LO    2048
#define W_BASE  8192
#define W_HI    (W_BASE)
#define W_LO    (W_BASE + 544)
#define T_HI    (W_BASE + 1088)
#define T_LO    (W_BASE + 1632)
#define SBUF_U32 10368        // 41.5 KB

__device__ __nv_bfloat16 g_Ahi[B_ * G_];
__device__ __nv_bfloat16 g_Alo[B_ * G_];
__device__ float g_dpart[B_ * NCTA];

__device__ __forceinline__ uint32_t smem_u32(const void* p) {
    uint32_t a;
    asm("{ .reg .u64 t; cvta.to.shared.u64 t, %1; cvt.u32.u64 %0, t; }"
        : "=r"(a) : "l"(p));
    return a;
}
#define CPA16(dst, src) \
    asm volatile("cp.async.cg.shared.global [%0], [%1], 16;" :: "r"(dst), "l"(src))
#define CPA_COMMIT() asm volatile("cp.async.commit_group;")
#define CPA_WAIT1()  asm volatile("cp.async.wait_group 1;")

__device__ __forceinline__ void mma_bf16(float* d, const uint32_t* a, uint32_t b0, uint32_t b1) {
    asm volatile(
        "mma.sync.aligned.m16n8k16.row.col.f32.bf16.bf16.f32 "
        "{%0,%1,%2,%3}, {%4,%5,%6,%7}, {%8,%9}, {%0,%1,%2,%3};"
        : "+f"(d[0]), "+f"(d[1]), "+f"(d[2]), "+f"(d[3])
        : "r"(a[0]), "r"(a[1]), "r"(a[2]), "r"(a[3]), "r"(b0), "r"(b1));
}

// split pair (x,y) -> packed bf16x2 hi and lo
__device__ __forceinline__ void split2p(float x, float y, uint32_t& hi, uint32_t& lo) {
    __nv_bfloat162 h2 = __float22bfloat162_rn(make_float2(x, y));
    uint32_t hu = *(uint32_t*)&h2;
    float hx = __uint_as_float(hu << 16);
    float hy = __uint_as_float(hu & 0xffff0000u);
    __nv_bfloat162 l2 = __float22bfloat162_rn(make_float2(x - hx, y - hy));
    hi = hu;
    lo = *(uint32_t*)&l2;
}

// ---------------- pre-split A: fp32 -> bf16 hi/lo globals ----------------
__global__ __launch_bounds__(256) void presplit_kernel(const float* __restrict__ A) {
    int i4 = blockIdx.x * 256 + threadIdx.x;   // 0..639999
    float4 v = ((const float4*)A)[i4];
    uint32_t h0, l0, h1, l1;
    split2p(v.x, v.y, h0, l0);
    split2p(v.z, v.w, h1, l1);
    ((uint2*)g_Ahi)[i4] = make_uint2(h0, h1);
    ((uint2*)g_Alo)[i4] = make_uint2(l0, l1);
}

// ---------------- fused main kernel ----------------
__global__ __launch_bounds__(256, 1) void bioxnet_fused_kernel(
    const float* __restrict__ mapp,
    const float* __restrict__ Wk,
    const float* __restrict__ Wa,
    const float* __restrict__ att_bias,
    const float* __restrict__ gamma,
    const float* __restrict__ beta,
    const float* __restrict__ dec_w,
    float* __restrict__ out_outcome,
    float* __restrict__ out_att)
{
    __shared__ __align__(16) uint32_t sbuf[SBUF_U32];
    __shared__ float redS[8][NT];
    __shared__ float redQ[8][NT];
    __shared__ float s_mean[NT];
    __shared__ float s_rstd[NT];

    const int tid  = threadIdx.x;
    const int lane = tid & 31;
    const int wrp  = tid >> 5;
    const int gr   = lane >> 2;   // 0..7
    const int tc   = lane & 3;    // 0..3
    const int wr   = wrp >> 1;    // 0..3 row group (32 rows)
    const int wc   = wrp & 1;     // 0..1 col group (16 cols)
    const int col0 = blockIdx.x * NT;

    const uint32_t sb = smem_u32(sbuf);

    // cp.async indices: 512 hi + 512 lo transfers of 16B, 4 per thread
    const int r0 = tid >> 2,         sg0 = tid & 3;
    const int r1 = (tid + 256) >> 2, sg1 = (tid + 256) & 3;
    const uint32_t dhi0 = sb + (r0 * SA + sg0 * 4) * 4;
    const uint32_t dhi1 = sb + (r1 * SA + sg1 * 4) * 4;
    const uint32_t dlo0 = dhi0 + A_LO * 4;
    const uint32_t dlo1 = dhi1 + A_LO * 4;
    const __nv_bfloat16* shi0 = g_Ahi + (long)r0 * G_ + sg0 * 8;
    const __nv_bfloat16* shi1 = g_Ahi + (long)r1 * G_ + sg1 * 8;
    const __nv_bfloat16* slo0 = g_Alo + (long)r0 * G_ + sg0 * 8;
    const __nv_bfloat16* slo1 = g_Alo + (long)r1 * G_ + sg1 * 8;

    // W prefetch addressing
    const int kr = tid >> 3;   // 0..31
    const int nv = tid & 7;    // 0..7
    const long gstep = (long)KT * P_;
    long goff = (long)kr * P_ + col0 + nv * 4;

    uint16_t* s16 = (uint16_t*)sbuf;
    const int n0 = nv * 4;

    float accH[2][2][4];
    float accT[2][2][4];
#pragma unroll
    for (int rt = 0; rt < 2; rt++)
#pragma unroll
        for (int nt = 0; nt < 2; nt++)
#pragma unroll
            for (int i = 0; i < 4; i++) { accH[rt][nt][i] = 0.f; accT[rt][nt][i] = 0.f; }

    // -------- prologue: chunk 0 --------
    CPA16(dhi0, shi0); CPA16(dhi1, shi1);
    CPA16(dlo0, slo0); CPA16(dlo1, slo1);
    CPA_COMMIT();
    float4 wk4 = *(const float4*)(Wk + goff);
    float4 mp4 = *(const float4*)(mapp + goff);
    float4 wa4 = *(const float4*)(Wa + goff);

#pragma unroll 1
    for (int i = 0; i < NCHUNK; i++) {
        const int s = i & 1;
        const uint32_t aBase = s * A_STAGE;

        __syncthreads();   // prev MMAs done reading W smem

        // ---- convert W regs (chunk i) -> smem bf16 hi/lo, transposed ----
        {
            float w0 = wk4.x * mp4.x, w1 = wk4.y * mp4.y;
            float w2 = wk4.z * mp4.z, w3 = wk4.w * mp4.w;
            uint32_t h, l;
            split2p(w0, w1, h, l);
            s16[W_HI*2 + (n0    )*SWW*2 + kr] = (uint16_t)h;
            s16[W_HI*2 + (n0 + 1)*SWW*2 + kr] = (uint16_t)(h >> 16);
            s16[W_LO*2 + (n0    )*SWW*2 + kr] = (uint16_t)l;
            s16[W_LO*2 + (n0 + 1)*SWW*2 + kr] = (uint16_t)(l >> 16);
            split2p(w2, w3, h, l);
            s16[W_HI*2 + (n0 + 2)*SWW*2 + kr] = (uint16_t)h;
            s16[W_HI*2 + (n0 + 3)*SWW*2 + kr] = (uint16_t)(h >> 16);
            s16[W_LO*2 + (n0 + 2)*SWW*2 + kr] = (uint16_t)l;
            s16[W_LO*2 + (n0 + 3)*SWW*2 + kr] = (uint16_t)(l >> 16);
            split2p(wa4.x, wa4.y, h, l);
            s16[T_HI*2 + (n0    )*SWW*2 + kr] = (uint16_t)h;
            s16[T_HI*2 + (n0 + 1)*SWW*2 + kr] = (uint16_t)(h >> 16);
            s16[T_LO*2 + (n0    )*SWW*2 + kr] = (uint16_t)l;
            s16[T_LO*2 + (n0 + 1)*SWW*2 + kr] = (uint16_t)(l >> 16);
            split2p(wa4.z, wa4.w, h, l);
            s16[T_HI*2 + (n0 + 2)*SWW*2 + kr] = (uint16_t)h;
            s16[T_HI*2 + (n0 + 3)*SWW*2 + kr] = (uint16_t)(h >> 16);
            s16[T_LO*2 + (n0 + 2)*SWW*2 + kr] = (uint16_t)l;
            s16[T_LO*2 + (n0 + 3)*SWW*2 + kr] = (uint16_t)(l >> 16);
        }

        // ---- prefetch chunk i+1 ----
        if (i + 1 < NCHUNK) {
            const int kk1 = (i + 1) * KT;
            const uint32_t nBase = (s ^ 1) * A_STAGE * 4;
            CPA16(dhi0 + nBase, shi0 + kk1); CPA16(dhi1 + nBase, shi1 + kk1);
            CPA16(dlo0 + nBase, slo0 + kk1); CPA16(dlo1 + nBase, slo1 + kk1);
            CPA_COMMIT();
            goff += gstep;
            wk4 = *(const float4*)(Wk + goff);
            mp4 = *(const float4*)(mapp + goff);
            wa4 = *(const float4*)(Wa + goff);
        } else {
            CPA_COMMIT();   // empty group keeps wait count uniform
        }
        CPA_WAIT1();        // chunk i A tiles arrived
        __syncthreads();    // A + W smem visible to all

        // ---- MMA phase on chunk i ----
#pragma unroll
        for (int kh = 0; kh < 16; kh += 8) {
            uint32_t ah[2][4], al[2][4];
#pragma unroll
            for (int rt = 0; rt < 2; rt++) {
                const int ab = aBase + (wr * 32 + rt * 16 + gr) * SA + kh + tc;
                ah[rt][0] = sbuf[ab];
                ah[rt][1] = sbuf[ab + 8 * SA];
                ah[rt][2] = sbuf[ab + 4];
                ah[rt][3] = sbuf[ab + 8 * SA + 4];
                al[rt][0] = sbuf[ab + A_LO];
                al[rt][1] = sbuf[ab + A_LO + 8 * SA];
                al[rt][2] = sbuf[ab + A_LO + 4];
                al[rt][3] = sbuf[ab + A_LO + 8 * SA + 4];
            }
#pragma unroll
            for (int nt = 0; nt < 2; nt++) {
                const int bb = (wc * 16 + nt * 8 + gr) * SWW + kh + tc;
                uint32_t wh0 = sbuf[W_HI + bb], wh1 = sbuf[W_HI + bb + 4];
                uint32_t wl0 = sbuf[W_LO + bb], wl1 = sbuf[W_LO + bb + 4];
                uint32_t th0 = sbuf[T_HI + bb], th1 = sbuf[T_HI + bb + 4];
                uint32_t tl0 = sbuf[T_LO + bb], tl1 = sbuf[T_LO + bb + 4];
#pragma unroll
                for (int rt = 0; rt < 2; rt++) {
                    mma_bf16(accH[rt][nt], ah[rt], wh0, wh1);
                    mma_bf16(accH[rt][nt], ah[rt], wl0, wl1);
                    mma_bf16(accH[rt][nt], al[rt], wh0, wh1);
                    mma_bf16(accT[rt][nt], ah[rt], th0, th1);
                    mma_bf16(accT[rt][nt], ah[rt], tl0, tl1);
                    mma_bf16(accT[rt][nt], al[rt], th0, th1);
                }
            }
        }
    }
    __syncthreads();

    // ---- spill accumulators (bias omitted: cancels in BN mean-subtract) ----
    float* sH = (float*)sbuf;
    float* sT = (float*)(sbuf + 4352);
#pragma unroll
    for (int rt = 0; rt < 2; rt++) {
#pragma unroll
        for (int nt = 0; nt < 2; nt++) {
            const int row0 = wr * 32 + rt * 16 + gr;
            const int col  = wc * 16 + nt * 8 + 2 * tc;
            *(float2*)&sH[(row0    ) * SHS + col] = make_float2(accH[rt][nt][0], accH[rt][nt][1]);
            *(float2*)&sH[(row0 + 8) * SHS + col] = make_float2(accH[rt][nt][2], accH[rt][nt][3]);
            *(float2*)&sT[(row0    ) * SHS + col] = make_float2(accT[rt][nt][0], accT[rt][nt][1]);
            *(float2*)&sT[(row0 + 8) * SHS + col] = make_float2(accT[rt][nt][2], accT[rt][nt][3]);
        }
    }
    __syncthreads();

    // ---- batchnorm stats over 128 rows (CTA-local) ----
    const int col = tid & 31;
    const int seg = tid >> 5;
    {
        float s = 0.f, q = 0.f;
#pragma unroll
        for (int r = 0; r < 16; r++) {
            float h = sH[(seg * 16 + r) * SHS + col];
            s += h; q += h * h;
        }
        redS[seg][col] = s;
        redQ[seg][col] = q;
    }
    __syncthreads();
    if (tid < 32) {
        float ss = 0.f, qq = 0.f;
#pragma unroll
        for (int i = 0; i < 8; i++) { ss += redS[i][tid]; qq += redQ[i][tid]; }
        float mean = ss * (1.0f / B_);
        float var  = qq * (1.0f / B_) - mean * mean;
        s_mean[tid] = mean;
        s_rstd[tid] = rsqrtf(var + BN_EPS);
    }
    __syncthreads();

    // ---- BN + tanh + sigmoid gate, outputs, decision partials ----
    const float mean = s_mean[col];
    const float rstd = s_rstd[col];
    const float gm = gamma[col0 + col];
    const float bt = beta[col0 + col];
    const float ab = att_bias[col0 + col];
    const float dw = dec_w[col0 + col];
#pragma unroll 4
    for (int r = 0; r < 16; r++) {
        int row = seg * 16 + r;
        float h  = sH[row * SHS + col];
        float hn = (h - mean) * rstd * gm + bt;
        float th = tanhf(hn);
        float z  = sT[row * SHS + col] + ab;
        float sg = 1.0f / (1.0f + __expf(-z));
        float o  = th * sg;
        long ofs = (long)row * P_ + col0 + col;
        out_outcome[ofs] = o;
        out_att[ofs]     = sg;
        float p = o * dw;
#pragma unroll
        for (int off = 16; off > 0; off >>= 1)
            p += __shfl_xor_sync(0xffffffffu, p, off);
        if (col == 0) g_dpart[row * NCTA + blockIdx.x] = p;
    }
}

__global__ __launch_bounds__(512) void bioxnet_decision_kernel(
    const float* __restrict__ dec_b, float* __restrict__ out_dec)
{
    __shared__ float red[4][B_];
    int t = threadIdx.x;
    int row = t >> 2;
    int seg = t & 3;
    const float4* p = (const float4*)(g_dpart + row * NCTA + seg * 32);
    float s = 0.f;
#pragma unroll
    for (int i = 0; i < 8; i++) {
        float4 v = p[i];
        s += v.x + v.y + v.z + v.w;
    }
    red[seg][row] = s;
    __syncthreads();
    if (t < B_) out_dec[t] = dec_b[0] + red[0][t] + red[1][t] + red[2][t] + red[3][t];
}

extern "C" void kernel_launch(void* const* d_in, const int* in_sizes, int n_in,
                              void* d_out, int out_size)
{
    (void)in_sizes; (void)n_in; (void)out_size;
    const float* A        = (const float*)d_in[0];
    const float* mapp     = (const float*)d_in[1];
    const float* Wk       = (const float*)d_in[2];
    // d_in[3] = bias: cancels exactly in batchnorm
    const float* Wa       = (const float*)d_in[4];
    const float* att_bias = (const float*)d_in[5];
    const float* gamma    = (const float*)d_in[6];
    const float* beta     = (const float*)d_in[7];
    const float* dec_w    = (const float*)d_in[8];
    const float* dec_b    = (const float*)d_in[9];

    float* out = (float*)d_out;
    float* out_outcome = out;
    float* out_dec     = out + (long)B_ * P_;
    float* out_att     = out + (long)B_ * P_ + B_;

    presplit_kernel<<<2500, 256>>>(A);
    bioxnet_fused_kernel<<<NCTA, 256>>>(mapp, Wk, Wa, att_bias,
                                        gamma, beta, dec_w,
                                        out_outcome, out_att);
    bioxnet_decision_kernel<<<1, 512>>>(dec_b, out_dec);
}

// round 5
// speedup vs baseline: 3.7305x; 1.5286x over previous
#include <cuda_runtime.h>
#include <cuda_fp16.h>
#include <stdint.h>

#define B_  128
#define G_  20000
#define P_  4096
#define KT  32
#define NT  32
#define NCTA   (P_/NT)     // 128
#define NCHUNK (G_/KT)     // 625 exact
#define BN_EPS 1e-5f

// dynamic smem byte offsets
#define A_ROWB    80                 // 32 halves (64B) + 16B pad -> stride 20 u32 (conflict-free)
#define A_ARR_B   (128*A_ROWB)       // 10240
#define A_LO_B    A_ARR_B
#define A_STAGE_B (2*A_ARR_B)        // 20480 (hi+lo)
#define W_BASE_B  (4*A_STAGE_B)      // 81920 (4 A stages)
#define W_ARR_B   (32*A_ROWB)        // 2560
#define T_OFF_B   W_ARR_B
#define W_STAGE_B (2*W_ARR_B)        // 5120 (W+T)
#define SMEM_DYN  (W_BASE_B + 2*W_STAGE_B + 256)   // ~92.4 KB
#define SHS 34                        // epilogue f32 row stride

__device__ __half g_Ahi[B_ * G_];
__device__ __half g_Alo[B_ * G_];
__device__ float g_dpart[B_ * NCTA];

__device__ __forceinline__ uint32_t smem_u32(const void* p) {
    uint32_t a;
    asm("{ .reg .u64 t; cvta.to.shared.u64 t, %1; cvt.u32.u64 %0, t; }"
        : "=r"(a) : "l"(p));
    return a;
}
#define CPA16(dst, src) \
    asm volatile("cp.async.cg.shared.global [%0], [%1], 16;" :: "r"(dst), "l"(src))
#define CPA_COMMIT() asm volatile("cp.async.commit_group;")
#define CPA_WAIT2()  asm volatile("cp.async.wait_group 2;")
#define CPA_WAIT0()  asm volatile("cp.async.wait_group 0;")

__device__ __forceinline__ void mma_f16(float* d, const uint32_t* a, uint32_t b0, uint32_t b1) {
    asm volatile(
        "mma.sync.aligned.m16n8k16.row.col.f32.f16.f16.f32 "
        "{%0,%1,%2,%3}, {%4,%5,%6,%7}, {%8,%9}, {%0,%1,%2,%3};"
        : "+f"(d[0]), "+f"(d[1]), "+f"(d[2]), "+f"(d[3])
        : "r"(a[0]), "r"(a[1]), "r"(a[2]), "r"(a[3]), "r"(b0), "r"(b1));
}

// ---------------- pre-split A: fp32 -> fp16 hi/lo globals ----------------
__global__ __launch_bounds__(256) void presplit_kernel(const float* __restrict__ A) {
    int i4 = blockIdx.x * 256 + threadIdx.x;   // 640000 float4s exactly
    float4 v = ((const float4*)A)[i4];
    __half2 h0 = __floats2half2_rn(v.x, v.y);
    float2 f0 = __half22float2(h0);
    __half2 l0 = __floats2half2_rn(v.x - f0.x, v.y - f0.y);
    __half2 h1 = __floats2half2_rn(v.z, v.w);
    float2 f1 = __half22float2(h1);
    __half2 l1 = __floats2half2_rn(v.z - f1.x, v.w - f1.y);
    ((uint2*)g_Ahi)[i4] = make_uint2(*(uint32_t*)&h0, *(uint32_t*)&h1);
    ((uint2*)g_Alo)[i4] = make_uint2(*(uint32_t*)&l0, *(uint32_t*)&l1);
}

// ---------------- fused main kernel ----------------
__global__ __launch_bounds__(256, 1) void bioxnet_fused_kernel(
    const float* __restrict__ mapp, const float* __restrict__ Wk,
    const float* __restrict__ Wa, const float* __restrict__ att_bias,
    const float* __restrict__ gamma, const float* __restrict__ beta,
    const float* __restrict__ dec_w,
    float* __restrict__ out_outcome, float* __restrict__ out_att)
{
    extern __shared__ __align__(16) char sp[];
    __shared__ float redS[8][NT], redQ[8][NT], s_mean[NT], s_rstd[NT];

    const int tid  = threadIdx.x;
    const int lane = tid & 31;
    const int wrp  = tid >> 5;
    const int gr   = lane >> 2;   // 0..7
    const int tc   = lane & 3;    // 0..3
    const int wr   = wrp >> 1;    // 0..3: 32-row group
    const int wc   = wrp & 1;     // 0..1: 16-col group
    const int col0 = blockIdx.x * NT;
    const uint32_t sb = smem_u32(sp);

    // A cp.async: thread -> (row, 2 of 4 16B units), 4 transfers/thread/chunk
    const int arow = tid >> 1;
    const int auh  = (tid & 1) * 2;
    const __half* gHi = g_Ahi + (long)arow * G_ + auh * 8;
    const __half* gLo = g_Alo + (long)arow * G_ + auh * 8;
    const uint32_t ad0 = (uint32_t)(arow * A_ROWB + auh * 16);

#define CPA_A(chunk, st) do {                                 \
        uint32_t _b = sb + (uint32_t)(st) * A_STAGE_B + ad0;  \
        const __half* _h = gHi + (chunk) * KT;                \
        const __half* _l = gLo + (chunk) * KT;                \
        CPA16(_b, _h);              CPA16(_b + 16, _h + 8);   \
        CPA16(_b + A_LO_B, _l);     CPA16(_b + A_LO_B + 16, _l + 8); \
    } while (0)

    // W prefetch: thread -> col wn, 4 k rows
    const int wn  = tid & 31;
    const int wkq = tid >> 5;   // 0..7
    float wkr[4], mpr[4], war[4];

#define LOAD_W(chunk) do {                                            \
        long _k = (long)(chunk) * KT + wkq * 4;                       \
        const float* _pw = Wk   + _k * P_ + col0 + wn;                \
        const float* _pm = mapp + _k * P_ + col0 + wn;                \
        const float* _pa = Wa   + _k * P_ + col0 + wn;                \
        _Pragma("unroll")                                             \
        for (int _j = 0; _j < 4; _j++) {                              \
            wkr[_j] = _pw[(long)_j * P_];                             \
            mpr[_j] = _pm[(long)_j * P_];                             \
            war[_j] = _pa[(long)_j * P_];                             \
        }                                                             \
    } while (0)

#define CONV_W(st) do {                                                         \
        uint32_t* _w = (uint32_t*)(sp + W_BASE_B + (st) * W_STAGE_B);           \
        uint32_t* _t = (uint32_t*)(sp + W_BASE_B + (st) * W_STAGE_B + T_OFF_B); \
        int _o = wn * 20 + wkq * 2;                                             \
        __half2 _p0 = __floats2half2_rn(wkr[0] * mpr[0], wkr[1] * mpr[1]);      \
        __half2 _p1 = __floats2half2_rn(wkr[2] * mpr[2], wkr[3] * mpr[3]);      \
        _w[_o] = *(uint32_t*)&_p0; _w[_o + 1] = *(uint32_t*)&_p1;               \
        _p0 = __floats2half2_rn(war[0], war[1]);                                \
        _p1 = __floats2half2_rn(war[2], war[3]);                                \
        _t[_o] = *(uint32_t*)&_p0; _t[_o + 1] = *(uint32_t*)&_p1;               \
    } while (0)

    float accH[2][2][4], accT[2][2][4];
#pragma unroll
    for (int rt = 0; rt < 2; rt++)
#pragma unroll
        for (int nt = 0; nt < 2; nt++)
#pragma unroll
            for (int i = 0; i < 4; i++) { accH[rt][nt][i] = 0.f; accT[rt][nt][i] = 0.f; }

    // -------- prologue --------
    CPA_A(0, 0); CPA_COMMIT();
    CPA_A(1, 1); CPA_COMMIT();
    LOAD_W(0);

#pragma unroll 1
    for (int i = 0; i < NCHUNK; i++) {
        CONV_W(i & 1);
        if (i + 1 < NCHUNK) LOAD_W(i + 1);
        if (i + 2 < NCHUNK) { CPA_A(i + 2, (i + 2) & 3); CPA_COMMIT(); CPA_WAIT2(); }
        else                { CPA_WAIT0(); }
        __syncthreads();   // A(i) + W(i) visible; also fences stage reuse (see ring analysis)

        const uint32_t* aHi = (const uint32_t*)(sp + (i & 3) * A_STAGE_B);
        const uint32_t* aLo = (const uint32_t*)(sp + (i & 3) * A_STAGE_B + A_LO_B);
        const uint32_t* wW  = (const uint32_t*)(sp + W_BASE_B + (i & 1) * W_STAGE_B);
        const uint32_t* wT  = (const uint32_t*)(sp + W_BASE_B + (i & 1) * W_STAGE_B + T_OFF_B);

#pragma unroll
        for (int kh = 0; kh < 2; kh++) {
            uint32_t ah[2][4], al[2][4];
#pragma unroll
            for (int rt = 0; rt < 2; rt++) {
                const int o = (wr * 32 + rt * 16 + gr) * 20 + kh * 8 + tc;
                ah[rt][0] = aHi[o];           al[rt][0] = aLo[o];
                ah[rt][1] = aHi[o + 160];     al[rt][1] = aLo[o + 160];   // +8 rows
                ah[rt][2] = aHi[o + 4];       al[rt][2] = aLo[o + 4];
                ah[rt][3] = aHi[o + 164];     al[rt][3] = aLo[o + 164];
            }
#pragma unroll
            for (int nt = 0; nt < 2; nt++) {
                const int o = (wc * 16 + nt * 8 + gr) * 20 + kh * 8 + tc;
                uint32_t w0 = wW[o], w1 = wW[o + 4];
                uint32_t t0 = wT[o], t1 = wT[o + 4];
#pragma unroll
                for (int rt = 0; rt < 2; rt++) {
                    mma_f16(accH[rt][nt], ah[rt], w0, w1);
                    mma_f16(accH[rt][nt], al[rt], w0, w1);
                    mma_f16(accT[rt][nt], ah[rt], t0, t1);
                    mma_f16(accT[rt][nt], al[rt], t0, t1);
                }
            }
        }
    }
    __syncthreads();

    // ---- spill accumulators (GEMM bias omitted: cancels in BN mean-subtract) ----
    float* sH = (float*)sp;
    float* sT = (float*)(sp + 17408);
#pragma unroll
    for (int rt = 0; rt < 2; rt++) {
#pragma unroll
        for (int nt = 0; nt < 2; nt++) {
            const int row0 = wr * 32 + rt * 16 + gr;
            const int col  = wc * 16 + nt * 8 + 2 * tc;
            *(float2*)&sH[(row0    ) * SHS + col] = make_float2(accH[rt][nt][0], accH[rt][nt][1]);
            *(float2*)&sH[(row0 + 8) * SHS + col] = make_float2(accH[rt][nt][2], accH[rt][nt][3]);
            *(float2*)&sT[(row0    ) * SHS + col] = make_float2(accT[rt][nt][0], accT[rt][nt][1]);
            *(float2*)&sT[(row0 + 8) * SHS + col] = make_float2(accT[rt][nt][2], accT[rt][nt][3]);
        }
    }
    __syncthreads();

    // ---- batchnorm stats over all 128 rows (CTA-local) ----
    const int col = tid & 31;
    const int seg = tid >> 5;
    {
        float s = 0.f, q = 0.f;
#pragma unroll
        for (int r = 0; r < 16; r++) {
            float h = sH[(seg * 16 + r) * SHS + col];
            s += h; q += h * h;
        }
        redS[seg][col] = s;
        redQ[seg][col] = q;
    }
    __syncthreads();
    if (tid < 32) {
        float ss = 0.f, qq = 0.f;
#pragma unroll
        for (int i = 0; i < 8; i++) { ss += redS[i][tid]; qq += redQ[i][tid]; }
        float mean = ss * (1.0f / B_);
        float var  = qq * (1.0f / B_) - mean * mean;
        s_mean[tid] = mean;
        s_rstd[tid] = rsqrtf(var + BN_EPS);
    }
    __syncthreads();

    // ---- BN + tanh + sigmoid gate, outputs, decision partials ----
    const float mean = s_mean[col], rstd = s_rstd[col];
    const float gm = gamma[col0 + col], bt = beta[col0 + col];
    const float ab = att_bias[col0 + col], dw = dec_w[col0 + col];
#pragma unroll 4
    for (int r = 0; r < 16; r++) {
        int row = seg * 16 + r;
        float h  = sH[row * SHS + col];
        float hn = (h - mean) * rstd * gm + bt;
        float th = tanhf(hn);
        float z  = sT[row * SHS + col] + ab;
        float sg = 1.0f / (1.0f + __expf(-z));
        float o  = th * sg;
        long ofs = (long)row * P_ + col0 + col;
        out_outcome[ofs] = o;
        out_att[ofs]     = sg;
        float p = o * dw;
#pragma unroll
        for (int off = 16; off > 0; off >>= 1)
            p += __shfl_xor_sync(0xffffffffu, p, off);
        if (col == 0) g_dpart[row * NCTA + blockIdx.x] = p;
    }
}

__global__ __launch_bounds__(512) void bioxnet_decision_kernel(
    const float* __restrict__ dec_b, float* __restrict__ out_dec)
{
    __shared__ float red[4][B_];
    int t = threadIdx.x;
    int row = t >> 2;
    int seg = t & 3;
    const float4* p = (const float4*)(g_dpart + row * NCTA + seg * 32);
    float s = 0.f;
#pragma unroll
    for (int i = 0; i < 8; i++) {
        float4 v = p[i];
        s += v.x + v.y + v.z + v.w;
    }
    red[seg][row] = s;
    __syncthreads();
    if (t < B_) out_dec[t] = dec_b[0] + red[0][t] + red[1][t] + red[2][t] + red[3][t];
}

extern "C" void kernel_launch(void* const* d_in, const int* in_sizes, int n_in,
                              void* d_out, int out_size)
{
    (void)in_sizes; (void)n_in; (void)out_size;
    const float* A        = (const float*)d_in[0];
    const float* mapp     = (const float*)d_in[1];
    const float* Wk       = (const float*)d_in[2];
    // d_in[3] = bias: cancels exactly in batchnorm mean subtraction
    const float* Wa       = (const float*)d_in[4];
    const float* att_bias = (const float*)d_in[5];
    const float* gamma    = (const float*)d_in[6];
    const float* beta     = (const float*)d_in[7];
    const float* dec_w    = (const float*)d_in[8];
    const float* dec_b    = (const float*)d_in[9];

    float* out = (float*)d_out;
    float* out_outcome = out;
    float* out_dec     = out + (long)B_ * P_;
    float* out_att     = out + (long)B_ * P_ + B_;

    cudaFuncSetAttribute(bioxnet_fused_kernel,
                         cudaFuncAttributeMaxDynamicSharedMemorySize, SMEM_DYN);

    presplit_kernel<<<2500, 256>>>(A);
    bioxnet_fused_kernel<<<NCTA, 256, SMEM_DYN>>>(mapp, Wk, Wa, att_bias,
                                                  gamma, beta, dec_w,
                                                  out_outcome, out_att);
    bioxnet_decision_kernel<<<1, 512>>>(dec_b, out_dec);
}

// round 6
// speedup vs baseline: 4.0908x; 1.0966x over previous
#include <cuda_runtime.h>
#include <cuda_fp16.h>
#include <stdint.h>

#define B_  128
#define G_  20000
#define P_  4096
#define KT  32
#define NT  32
#define NCTA   (P_/NT)     // 128
#define NCHUNK (G_/KT)     // 625 exact
#define BN_EPS 1e-5f

// dynamic smem byte offsets
#define A_ROWB    80                 // 32 halves (64B) + 16B pad -> u32 stride 20, conflict-free
#define A_STAGE_B (128*A_ROWB)       // 10240 per stage
#define W_BASE_B  (4*A_STAGE_B)      // 40960 (4 A stages)
#define W_ARR_B   (32*A_ROWB)        // 2560
#define T_OFF_B   W_ARR_B
#define W_STAGE_B (2*W_ARR_B)        // 5120 (W+T)
#define SMEM_DYN  (W_BASE_B + 2*W_STAGE_B + 256)   // ~51.5 KB
#define SHS 34                        // epilogue f32 row stride

__device__ __half g_Ah[B_ * G_];
__device__ float g_dpart[B_ * NCTA];

__device__ __forceinline__ uint32_t smem_u32(const void* p) {
    uint32_t a;
    asm("{ .reg .u64 t; cvta.to.shared.u64 t, %1; cvt.u32.u64 %0, t; }"
        : "=r"(a) : "l"(p));
    return a;
}
#define CPA16(dst, src) \
    asm volatile("cp.async.cg.shared.global [%0], [%1], 16;" :: "r"(dst), "l"(src))
#define CPA_COMMIT() asm volatile("cp.async.commit_group;")
#define CPA_WAIT2()  asm volatile("cp.async.wait_group 2;")
#define CPA_WAIT0()  asm volatile("cp.async.wait_group 0;")

__device__ __forceinline__ void mma_f16(float* d, const uint32_t* a, uint32_t b0, uint32_t b1) {
    asm volatile(
        "mma.sync.aligned.m16n8k16.row.col.f32.f16.f16.f32 "
        "{%0,%1,%2,%3}, {%4,%5,%6,%7}, {%8,%9}, {%0,%1,%2,%3};"
        : "+f"(d[0]), "+f"(d[1]), "+f"(d[2]), "+f"(d[3])
        : "r"(a[0]), "r"(a[1]), "r"(a[2]), "r"(a[3]), "r"(b0), "r"(b1));
}

// ---------------- pre-convert A: fp32 -> fp16 global ----------------
__global__ __launch_bounds__(256) void presplit_kernel(const float* __restrict__ A) {
    int i4 = blockIdx.x * 256 + threadIdx.x;   // 640000 float4s exactly
    float4 v = ((const float4*)A)[i4];
    __half2 h0 = __floats2half2_rn(v.x, v.y);
    __half2 h1 = __floats2half2_rn(v.z, v.w);
    ((uint2*)g_Ah)[i4] = make_uint2(*(uint32_t*)&h0, *(uint32_t*)&h1);
}

// ---------------- fused main kernel ----------------
__global__ __launch_bounds__(256, 1) void bioxnet_fused_kernel(
    const float* __restrict__ mapp, const float* __restrict__ Wk,
    const float* __restrict__ Wa, const float* __restrict__ att_bias,
    const float* __restrict__ gamma, const float* __restrict__ beta,
    const float* __restrict__ dec_w,
    float* __restrict__ out_outcome, float* __restrict__ out_att)
{
    extern __shared__ __align__(16) char sp[];
    __shared__ float redS[8][NT], redQ[8][NT], s_mean[NT], s_rstd[NT];

    const int tid  = threadIdx.x;
    const int lane = tid & 31;
    const int wrp  = tid >> 5;
    const int gr   = lane >> 2;   // 0..7
    const int tc   = lane & 3;    // 0..3
    const int wr   = wrp >> 1;    // 0..3: 32-row group
    const int wc   = wrp & 1;     // 0..1: 16-col group
    const int col0 = blockIdx.x * NT;
    const uint32_t sb = smem_u32(sp);

    // A cp.async: thread -> (row = tid>>1, 2 of 4 16B units), 2 transfers/thread/chunk
    const int arow = tid >> 1;
    const int auh  = (tid & 1) * 2;
    const __half* gH = g_Ah + (long)arow * G_ + auh * 8;
    const uint32_t ad0 = (uint32_t)(arow * A_ROWB + auh * 16);

#define CPA_A(chunk, st) do {                                 \
        uint32_t _b = sb + (uint32_t)(st) * A_STAGE_B + ad0;  \
        const __half* _h = gH + (chunk) * KT;                 \
        CPA16(_b, _h);  CPA16(_b + 16, _h + 8);               \
    } while (0)

    // W prefetch: thread -> col wn, 4 k rows
    const int wn  = tid & 31;
    const int wkq = tid >> 5;   // 0..7
    float wkr[4], mpr[4], war[4];

#define LOAD_W(chunk) do {                                            \
        long _k = (long)(chunk) * KT + wkq * 4;                       \
        const float* _pw = Wk   + _k * P_ + col0 + wn;                \
        const float* _pm = mapp + _k * P_ + col0 + wn;                \
        const float* _pa = Wa   + _k * P_ + col0 + wn;                \
        _Pragma("unroll")                                             \
        for (int _j = 0; _j < 4; _j++) {                              \
            wkr[_j] = _pw[(long)_j * P_];                             \
            mpr[_j] = _pm[(long)_j * P_];                             \
            war[_j] = _pa[(long)_j * P_];                             \
        }                                                             \
    } while (0)

#define CONV_W(st) do {                                                         \
        uint32_t* _w = (uint32_t*)(sp + W_BASE_B + (st) * W_STAGE_B);           \
        uint32_t* _t = (uint32_t*)(sp + W_BASE_B + (st) * W_STAGE_B + T_OFF_B); \
        int _o = wn * 20 + wkq * 2;                                             \
        __half2 _p0 = __floats2half2_rn(wkr[0] * mpr[0], wkr[1] * mpr[1]);      \
        __half2 _p1 = __floats2half2_rn(wkr[2] * mpr[2], wkr[3] * mpr[3]);      \
        _w[_o] = *(uint32_t*)&_p0; _w[_o + 1] = *(uint32_t*)&_p1;               \
        _p0 = __floats2half2_rn(war[0], war[1]);                                \
        _p1 = __floats2half2_rn(war[2], war[3]);                                \
        _t[_o] = *(uint32_t*)&_p0; _t[_o + 1] = *(uint32_t*)&_p1;               \
    } while (0)

    float accH[2][2][4], accT[2][2][4];
#pragma unroll
    for (int rt = 0; rt < 2; rt++)
#pragma unroll
        for (int nt = 0; nt < 2; nt++)
#pragma unroll
            for (int i = 0; i < 4; i++) { accH[rt][nt][i] = 0.f; accT[rt][nt][i] = 0.f; }

    // -------- prologue --------
    CPA_A(0, 0); CPA_COMMIT();
    CPA_A(1, 1); CPA_COMMIT();
    LOAD_W(0);

#pragma unroll 1
    for (int i = 0; i < NCHUNK; i++) {
        CONV_W(i & 1);
        if (i + 1 < NCHUNK) LOAD_W(i + 1);
        if (i + 2 < NCHUNK) { CPA_A(i + 2, (i + 2) & 3); CPA_COMMIT(); CPA_WAIT2(); }
        else                { CPA_WAIT0(); }
        __syncthreads();   // A(i)+W(i) visible; ring-reuse fenced by prior barriers

        const uint32_t* aH = (const uint32_t*)(sp + (i & 3) * A_STAGE_B);
        const uint32_t* wW = (const uint32_t*)(sp + W_BASE_B + (i & 1) * W_STAGE_B);
        const uint32_t* wT = (const uint32_t*)(sp + W_BASE_B + (i & 1) * W_STAGE_B + T_OFF_B);

#pragma unroll
        for (int kh = 0; kh < 2; kh++) {
            uint32_t ah[2][4];
#pragma unroll
            for (int rt = 0; rt < 2; rt++) {
                const int o = (wr * 32 + rt * 16 + gr) * 20 + kh * 8 + tc;
                ah[rt][0] = aH[o];
                ah[rt][1] = aH[o + 160];   // +8 rows
                ah[rt][2] = aH[o + 4];     // +8 k
                ah[rt][3] = aH[o + 164];
            }
#pragma unroll
            for (int nt = 0; nt < 2; nt++) {
                const int o = (wc * 16 + nt * 8 + gr) * 20 + kh * 8 + tc;
                uint32_t w0 = wW[o], w1 = wW[o + 4];
                uint32_t t0 = wT[o], t1 = wT[o + 4];
#pragma unroll
                for (int rt = 0; rt < 2; rt++) {
                    mma_f16(accH[rt][nt], ah[rt], w0, w1);
                    mma_f16(accT[rt][nt], ah[rt], t0, t1);
                }
            }
        }
    }
    __syncthreads();

    // ---- spill accumulators (GEMM bias omitted: cancels in BN mean-subtract) ----
    float* sH = (float*)sp;
    float* sT = (float*)(sp + 17408);
#pragma unroll
    for (int rt = 0; rt < 2; rt++) {
#pragma unroll
        for (int nt = 0; nt < 2; nt++) {
            const int row0 = wr * 32 + rt * 16 + gr;
            const int col  = wc * 16 + nt * 8 + 2 * tc;
            *(float2*)&sH[(row0    ) * SHS + col] = make_float2(accH[rt][nt][0], accH[rt][nt][1]);
            *(float2*)&sH[(row0 + 8) * SHS + col] = make_float2(accH[rt][nt][2], accH[rt][nt][3]);
            *(float2*)&sT[(row0    ) * SHS + col] = make_float2(accT[rt][nt][0], accT[rt][nt][1]);
            *(float2*)&sT[(row0 + 8) * SHS + col] = make_float2(accT[rt][nt][2], accT[rt][nt][3]);
        }
    }
    __syncthreads();

    // ---- batchnorm stats over all 128 rows (CTA-local) ----
    const int col = tid & 31;
    const int seg = tid >> 5;
    {
        float s = 0.f, q = 0.f;
#pragma unroll
        for (int r = 0; r < 16; r++) {
            float h = sH[(seg * 16 + r) * SHS + col];
            s += h; q += h * h;
        }
        redS[seg][col] = s;
        redQ[seg][col] = q;
    }
    __syncthreads();
    if (tid < 32) {
        float ss = 0.f, qq = 0.f;
#pragma unroll
        for (int i = 0; i < 8; i++) { ss += redS[i][tid]; qq += redQ[i][tid]; }
        float mean = ss * (1.0f / B_);
        float var  = qq * (1.0f / B_) - mean * mean;
        s_mean[tid] = mean;
        s_rstd[tid] = rsqrtf(var + BN_EPS);
    }
    __syncthreads();

    // ---- BN + tanh + sigmoid gate, outputs, decision partials ----
    const float mean = s_mean[col], rstd = s_rstd[col];
    const float gm = gamma[col0 + col], bt = beta[col0 + col];
    const float ab = att_bias[col0 + col], dw = dec_w[col0 + col];
#pragma unroll 4
    for (int r = 0; r < 16; r++) {
        int row = seg * 16 + r;
        float h  = sH[row * SHS + col];
        float hn = (h - mean) * rstd * gm + bt;
        float th = tanhf(hn);
        float z  = sT[row * SHS + col] + ab;
        float sg = 1.0f / (1.0f + __expf(-z));
        float o  = th * sg;
        long ofs = (long)row * P_ + col0 + col;
        out_outcome[ofs] = o;
        out_att[ofs]     = sg;
        float p = o * dw;
#pragma unroll
        for (int off = 16; off > 0; off >>= 1)
            p += __shfl_xor_sync(0xffffffffu, p, off);
        if (col == 0) g_dpart[row * NCTA + blockIdx.x] = p;
    }
}

__global__ __launch_bounds__(512) void bioxnet_decision_kernel(
    const float* __restrict__ dec_b, float* __restrict__ out_dec)
{
    __shared__ float red[4][B_];
    int t = threadIdx.x;
    int row = t >> 2;
    int seg = t & 3;
    const float4* p = (const float4*)(g_dpart + row * NCTA + seg * 32);
    float s = 0.f;
#pragma unroll
    for (int i = 0; i < 8; i++) {
        float4 v = p[i];
        s += v.x + v.y + v.z + v.w;
    }
    red[seg][row] = s;
    __syncthreads();
    if (t < B_) out_dec[t] = dec_b[0] + red[0][t] + red[1][t] + red[2][t] + red[3][t];
}

extern "C" void kernel_launch(void* const* d_in, const int* in_sizes, int n_in,
                              void* d_out, int out_size)
{
    (void)in_sizes; (void)n_in; (void)out_size;
    const float* A        = (const float*)d_in[0];
    const float* mapp     = (const float*)d_in[1];
    const float* Wk       = (const float*)d_in[2];
    // d_in[3] = bias: cancels exactly in batchnorm mean subtraction
    const float* Wa       = (const float*)d_in[4];
    const float* att_bias = (const float*)d_in[5];
    const float* gamma    = (const float*)d_in[6];
    const float* beta     = (const float*)d_in[7];
    const float* dec_w    = (const float*)d_in[8];
    const float* dec_b    = (const float*)d_in[9];

    float* out = (float*)d_out;
    float* out_outcome = out;
    float* out_dec     = out + (long)B_ * P_;
    float* out_att     = out + (long)B_ * P_ + B_;

    cudaFuncSetAttribute(bioxnet_fused_kernel,
                         cudaFuncAttributeMaxDynamicSharedMemorySize, SMEM_DYN);

    presplit_kernel<<<2500, 256>>>(A);
    bioxnet_fused_kernel<<<NCTA, 256, SMEM_DYN>>>(mapp, Wk, Wa, att_bias,
                                                  gamma, beta, dec_w,
                                                  out_outcome, out_att);
    bioxnet_decision_kernel<<<1, 512>>>(dec_b, out_dec);
}

// round 7
// speedup vs baseline: 4.9048x; 1.1990x over previous
#include <cuda_runtime.h>
#include <cuda_fp16.h>
#include <stdint.h>

#define B_  128
#define G_  20000
#define P_  4096
#define KT  32
#define NT  32
#define NCTA   (P_/NT)     // 128
#define NCHUNK (G_/KT)     // 625 exact
#define BN_EPS 1e-5f

// dynamic smem byte offsets
#define A_ROWB     80                  // 32 halves + 16B pad -> u32 stride 20, conflict-free
#define A_STAGE_B  (128*A_ROWB)        // 10240 per A stage, ring of 4
#define WF32_BASE  (4*A_STAGE_B)       // 40960
#define WF32_STAGE 12288               // Wk 4KB | mapp 4KB | Wa 4KB, ring of 4
#define WF16_BASE  (WF32_BASE + 4*WF32_STAGE)   // 90112
#define W_ARR_B    2560                // fp16 [n][k] stride-20 array
#define WF16_STAGE (2*W_ARR_B)         // W + T, ring of 2
#define SMEM_DYN   (WF16_BASE + 2*WF16_STAGE + 256)   // ~98.5 KB
#define SHS 34                          // epilogue f32 row stride

__device__ __half g_Ah[B_ * G_];
__device__ float g_dpart[B_ * NCTA];

__device__ __forceinline__ uint32_t smem_u32(const void* p) {
    uint32_t a;
    asm("{ .reg .u64 t; cvta.to.shared.u64 t, %1; cvt.u32.u64 %0, t; }"
        : "=r"(a) : "l"(p));
    return a;
}
#define CPA16(dst, src) \
    asm volatile("cp.async.cg.shared.global [%0], [%1], 16;" :: "r"(dst), "l"(src))
#define CPA_COMMIT() asm volatile("cp.async.commit_group;")
#define CPA_WAIT2()  asm volatile("cp.async.wait_group 2;")

__device__ __forceinline__ void mma_f16(float* d, const uint32_t* a, uint32_t b0, uint32_t b1) {
    asm volatile(
        "mma.sync.aligned.m16n8k16.row.col.f32.f16.f16.f32 "
        "{%0,%1,%2,%3}, {%4,%5,%6,%7}, {%8,%9}, {%0,%1,%2,%3};"
        : "+f"(d[0]), "+f"(d[1]), "+f"(d[2]), "+f"(d[3])
        : "r"(a[0]), "r"(a[1]), "r"(a[2]), "r"(a[3]), "r"(b0), "r"(b1));
}

// ---------------- pre-convert A: fp32 -> fp16 global ----------------
__global__ __launch_bounds__(256) void presplit_kernel(const float* __restrict__ A) {
    int i4 = blockIdx.x * 256 + threadIdx.x;   // 640000 float4s exactly
    float4 v = ((const float4*)A)[i4];
    __half2 h0 = __floats2half2_rn(v.x, v.y);
    __half2 h1 = __floats2half2_rn(v.z, v.w);
    ((uint2*)g_Ah)[i4] = make_uint2(*(uint32_t*)&h0, *(uint32_t*)&h1);
}

// ---------------- fused main kernel ----------------
__global__ __launch_bounds__(256, 1) void bioxnet_fused_kernel(
    const float* __restrict__ mapp, const float* __restrict__ Wk,
    const float* __restrict__ Wa, const float* __restrict__ att_bias,
    const float* __restrict__ gamma, const float* __restrict__ beta,
    const float* __restrict__ dec_w,
    float* __restrict__ out_outcome, float* __restrict__ out_att)
{
    extern __shared__ __align__(16) char sp[];
    __shared__ float redS[8][NT], redQ[8][NT], s_mean[NT], s_rstd[NT];

    const int tid  = threadIdx.x;
    const int lane = tid & 31;
    const int wrp  = tid >> 5;
    const int gr   = lane >> 2;   // 0..7
    const int tc   = lane & 3;    // 0..3
    const int wr   = wrp >> 1;    // 0..3: 32-row group
    const int wc   = wrp & 1;     // 0..1: 16-col group
    const int col0 = blockIdx.x * NT;
    const uint32_t sb = smem_u32(sp);

    // A cp.async: thread -> (row = tid>>1, 2 of 4 16B units)
    const int arow = tid >> 1;
    const int auh  = (tid & 1) * 2;
    const __half* gH = g_Ah + (long)arow * G_ + auh * 8;
    const uint32_t ad0 = (uint32_t)(arow * A_ROWB + auh * 16);

#define CPA_A(chunk, st) do {                                 \
        uint32_t _b = sb + (uint32_t)(st) * A_STAGE_B + ad0;  \
        const __half* _h = gH + (chunk) * KT;                 \
        CPA16(_b, _h);  CPA16(_b + 16, _h + 8);               \
    } while (0)

    // W cp.async: thread -> row wkr0 = tid>>3, 16B unit wc0 = tid&7, one per array
    const int wkr0 = tid >> 3;
    const int wc0  = tid & 7;
    const long wgo = (long)wkr0 * P_ + col0 + wc0 * 4;
    const uint32_t wd0 = (uint32_t)(wkr0 * 128 + wc0 * 16);

#define CPA_W(chunk, st) do {                                         \
        uint32_t _b = sb + WF32_BASE + (uint32_t)(st) * WF32_STAGE + wd0; \
        long _g = (long)(chunk) * KT * P_ + wgo;                      \
        CPA16(_b,         Wk   + _g);                                 \
        CPA16(_b + 4096,  mapp + _g);                                 \
        CPA16(_b + 8192,  Wa   + _g);                                 \
    } while (0)

    // CONV: thread -> col wn, 4 k rows starting wkq*4 (reads staged fp32)
    const int wn  = tid & 31;
    const int wkq = tid >> 5;   // 0..7

#define CONV_W(st32, st16) do {                                                   \
        const float* _f = (const float*)(sp + WF32_BASE + (st32) * WF32_STAGE);   \
        uint32_t* _w = (uint32_t*)(sp + WF16_BASE + (st16) * WF16_STAGE);         \
        uint32_t* _t = _w + (W_ARR_B / 4);                                        \
        const int _k0 = wkq * 4;                                                  \
        float _a0 = _f[(_k0    ) * 32 + wn], _m0 = _f[1024 + (_k0    ) * 32 + wn];\
        float _a1 = _f[(_k0 + 1) * 32 + wn], _m1 = _f[1024 + (_k0 + 1) * 32 + wn];\
        float _a2 = _f[(_k0 + 2) * 32 + wn], _m2 = _f[1024 + (_k0 + 2) * 32 + wn];\
        float _a3 = _f[(_k0 + 3) * 32 + wn], _m3 = _f[1024 + (_k0 + 3) * 32 + wn];\
        int _o = wn * 20 + wkq * 2;                                               \
        __half2 _p0 = __floats2half2_rn(_a0 * _m0, _a1 * _m1);                    \
        __half2 _p1 = __floats2half2_rn(_a2 * _m2, _a3 * _m3);                    \
        _w[_o] = *(uint32_t*)&_p0; _w[_o + 1] = *(uint32_t*)&_p1;                 \
        _a0 = _f[2048 + (_k0    ) * 32 + wn];                                     \
        _a1 = _f[2048 + (_k0 + 1) * 32 + wn];                                     \
        _a2 = _f[2048 + (_k0 + 2) * 32 + wn];                                     \
        _a3 = _f[2048 + (_k0 + 3) * 32 + wn];                                     \
        _p0 = __floats2half2_rn(_a0, _a1);                                        \
        _p1 = __floats2half2_rn(_a2, _a3);                                        \
        _t[_o] = *(uint32_t*)&_p0; _t[_o + 1] = *(uint32_t*)&_p1;                 \
    } while (0)

    float accH[2][2][4], accT[2][2][4];
#pragma unroll
    for (int rt = 0; rt < 2; rt++)
#pragma unroll
        for (int nt = 0; nt < 2; nt++)
#pragma unroll
            for (int i = 0; i < 4; i++) { accH[rt][nt][i] = 0.f; accT[rt][nt][i] = 0.f; }

    // -------- prologue: 3 chunks in flight --------
    CPA_A(0, 0); CPA_W(0, 0); CPA_COMMIT();
    CPA_A(1, 1); CPA_W(1, 1); CPA_COMMIT();
    CPA_A(2, 2); CPA_W(2, 2); CPA_COMMIT();

#pragma unroll 1
    for (int i = 0; i < NCHUNK; i++) {
        CPA_WAIT2();       // group i complete (pending: i, i+1, i+2)
        __syncthreads();   // all warps past MMA(i-1); chunk i visible everywhere

        // prefetch chunk i+3 into the stage MMA(i-1) just vacated
        if (i + 3 < NCHUNK) { CPA_A(i + 3, (i + 3) & 3); CPA_W(i + 3, (i + 3) & 3); }
        CPA_COMMIT();      // unconditional: keeps group count uniform

        CONV_W(i & 3, i & 1);
        __syncthreads();   // fp16 W/T visible before MMA

        const uint32_t* aH = (const uint32_t*)(sp + (i & 3) * A_STAGE_B);
        const uint32_t* wW = (const uint32_t*)(sp + WF16_BASE + (i & 1) * WF16_STAGE);
        const uint32_t* wT = wW + (W_ARR_B / 4);

#pragma unroll
        for (int kh = 0; kh < 2; kh++) {
            uint32_t ah[2][4];
#pragma unroll
            for (int rt = 0; rt < 2; rt++) {
                const int o = (wr * 32 + rt * 16 + gr) * 20 + kh * 8 + tc;
                ah[rt][0] = aH[o];
                ah[rt][1] = aH[o + 160];   // +8 rows
                ah[rt][2] = aH[o + 4];     // +8 k
                ah[rt][3] = aH[o + 164];
            }
#pragma unroll
            for (int nt = 0; nt < 2; nt++) {
                const int o = (wc * 16 + nt * 8 + gr) * 20 + kh * 8 + tc;
                uint32_t w0 = wW[o], w1 = wW[o + 4];
                uint32_t t0 = wT[o], t1 = wT[o + 4];
#pragma unroll
                for (int rt = 0; rt < 2; rt++) {
                    mma_f16(accH[rt][nt], ah[rt], w0, w1);
                    mma_f16(accT[rt][nt], ah[rt], t0, t1);
                }
            }
        }
    }
    __syncthreads();

    // ---- spill accumulators (GEMM bias omitted: cancels in BN mean-subtract) ----
    float* sH = (float*)sp;
    float* sT = (float*)(sp + 17408);
#pragma unroll
    for (int rt = 0; rt < 2; rt++) {
#pragma unroll
        for (int nt = 0; nt < 2; nt++) {
            const int row0 = wr * 32 + rt * 16 + gr;
            const int col  = wc * 16 + nt * 8 + 2 * tc;
            *(float2*)&sH[(row0    ) * SHS + col] = make_float2(accH[rt][nt][0], accH[rt][nt][1]);
            *(float2*)&sH[(row0 + 8) * SHS + col] = make_float2(accH[rt][nt][2], accH[rt][nt][3]);
            *(float2*)&sT[(row0    ) * SHS + col] = make_float2(accT[rt][nt][0], accT[rt][nt][1]);
            *(float2*)&sT[(row0 + 8) * SHS + col] = make_float2(accT[rt][nt][2], accT[rt][nt][3]);
        }
    }
    __syncthreads();

    // ---- batchnorm stats over all 128 rows (CTA-local) ----
    const int col = tid & 31;
    const int seg = tid >> 5;
    {
        float s = 0.f, q = 0.f;
#pragma unroll
        for (int r = 0; r < 16; r++) {
            float h = sH[(seg * 16 + r) * SHS + col];
            s += h; q += h * h;
        }
        redS[seg][col] = s;
        redQ[seg][col] = q;
    }
    __syncthreads();
    if (tid < 32) {
        float ss = 0.f, qq = 0.f;
#pragma unroll
        for (int i = 0; i < 8; i++) { ss += redS[i][tid]; qq += redQ[i][tid]; }
        float mean = ss * (1.0f / B_);
        float var  = qq * (1.0f / B_) - mean * mean;
        s_mean[tid] = mean;
        s_rstd[tid] = rsqrtf(var + BN_EPS);
    }
    __syncthreads();

    // ---- BN + tanh + sigmoid gate, outputs, decision partials ----
    const float mean = s_mean[col], rstd = s_rstd[col];
    const float gm = gamma[col0 + col], bt = beta[col0 + col];
    const float ab = att_bias[col0 + col], dw = dec_w[col0 + col];
#pragma unroll 4
    for (int r = 0; r < 16; r++) {
        int row = seg * 16 + r;
        float h  = sH[row * SHS + col];
        float hn = (h - mean) * rstd * gm + bt;
        float th = tanhf(hn);
        float z  = sT[row * SHS + col] + ab;
        float sg = 1.0f / (1.0f + __expf(-z));
        float o  = th * sg;
        long ofs = (long)row * P_ + col0 + col;
        out_outcome[ofs] = o;
        out_att[ofs]     = sg;
        float p = o * dw;
#pragma unroll
        for (int off = 16; off > 0; off >>= 1)
            p += __shfl_xor_sync(0xffffffffu, p, off);
        if (col == 0) g_dpart[row * NCTA + blockIdx.x] = p;
    }
}

__global__ __launch_bounds__(512) void bioxnet_decision_kernel(
    const float* __restrict__ dec_b, float* __restrict__ out_dec)
{
    __shared__ float red[4][B_];
    int t = threadIdx.x;
    int row = t >> 2;
    int seg = t & 3;
    const float4* p = (const float4*)(g_dpart + row * NCTA + seg * 32);
    float s = 0.f;
#pragma unroll
    for (int i = 0; i < 8; i++) {
        float4 v = p[i];
        s += v.x + v.y + v.z + v.w;
    }
    red[seg][row] = s;
    __syncthreads();
    if (t < B_) out_dec[t] = dec_b[0] + red[0][t] + red[1][t] + red[2][t] + red[3][t];
}

extern "C" void kernel_launch(void* const* d_in, const int* in_sizes, int n_in,
                              void* d_out, int out_size)
{
    (void)in_sizes; (void)n_in; (void)out_size;
    const float* A        = (const float*)d_in[0];
    const float* mapp     = (const float*)d_in[1];
    const float* Wk       = (const float*)d_in[2];
    // d_in[3] = bias: cancels exactly in batchnorm mean subtraction
    const float* Wa       = (const float*)d_in[4];
    const float* att_bias = (const float*)d_in[5];
    const float* gamma    = (const float*)d_in[6];
    const float* beta     = (const float*)d_in[7];
    const float* dec_w    = (const float*)d_in[8];
    const float* dec_b    = (const float*)d_in[9];

    float* out = (float*)d_out;
    float* out_outcome = out;
    float* out_dec     = out + (long)B_ * P_;
    float* out_att     = out + (long)B_ * P_ + B_;

    cudaFuncSetAttribute(bioxnet_fused_kernel,
                         cudaFuncAttributeMaxDynamicSharedMemorySize, SMEM_DYN);

    presplit_kernel<<<2500, 256>>>(A);
    bioxnet_fused_kernel<<<NCTA, 256, SMEM_DYN>>>(mapp, Wk, Wa, att_bias,
                                                  gamma, beta, dec_w,
                                                  out_outcome, out_att);
    bioxnet_decision_kernel<<<1, 512>>>(dec_b, out_dec);
}